// round 14
// baseline (speedup 1.0000x reference)
#include <cuda_runtime.h>
#include <cuda_fp16.h>
#include <stdint.h>
#include <math.h>

// ---------------------------------------------------------------------------
// Fused 5-layer MLP (32->64->64->64->64->3, ReLU hidden, sigmoid out).
// mma.sync m16n8k16 fp16-in/fp16-accum hidden layers, fp32-accum final MMA.
// TWO INDEPENDENT 32-ROW STREAMS PER WARP, interleaved block-wise:
//   epi_k(s0); L_{k+1}(s0); epi_k(s1); L_{k+1}(s1); ...
// Every epilogue's accumulators finished one 64-MMA block ago (no result
// waits); every A-dependency hides under the other stream/warp. 256-thread
// CTA, 1 CTA/SM (182KB smem), ~175 regs, warp-private cp.async X buffers.
// ---------------------------------------------------------------------------

#define FH_OFF     0
#define XB_OFF     32768
#define XB_STRIDE  36
#define XW_FLOATS  (32 * XB_STRIDE)          // 1152 floats per 32-row buffer
#define XW_BYTES   (XW_FLOATS * 4)           // 4608
#define FH4_OFF    (XB_OFF + 8 * 4 * XW_BYTES)   // 32768 + 147456 = 180224
#define BIH_OFF    (FH4_OFF + 1024)
#define B4P_OFF    (BIH_OFF + 512)
#define SMEM_BYTES (B4P_OFF + 32)

__device__ __forceinline__ void mma_h_acc(uint32_t c[2], const uint32_t a[4],
                                          uint32_t b0, uint32_t b1) {
    asm volatile(
        "mma.sync.aligned.m16n8k16.row.col.f16.f16.f16.f16 "
        "{%0,%1},{%2,%3,%4,%5},{%6,%7},{%0,%1};"
        : "+r"(c[0]), "+r"(c[1])
        : "r"(a[0]), "r"(a[1]), "r"(a[2]), "r"(a[3]), "r"(b0), "r"(b1));
}
__device__ __forceinline__ void mma_h_init(uint32_t c[2], const uint32_t a[4],
                                           uint32_t b0, uint32_t b1) {
    const uint32_t z = 0;
    asm volatile(
        "mma.sync.aligned.m16n8k16.row.col.f16.f16.f16.f16 "
        "{%0,%1},{%2,%3,%4,%5},{%6,%7},{%8,%8};"
        : "=r"(c[0]), "=r"(c[1])
        : "r"(a[0]), "r"(a[1]), "r"(a[2]), "r"(a[3]), "r"(b0), "r"(b1), "r"(z));
}
__device__ __forceinline__ void mma_f_acc(float c[4], const uint32_t a[4],
                                          uint32_t b0, uint32_t b1) {
    asm volatile(
        "mma.sync.aligned.m16n8k16.row.col.f32.f16.f16.f32 "
        "{%0,%1,%2,%3},{%4,%5,%6,%7},{%8,%9},{%0,%1,%2,%3};"
        : "+f"(c[0]), "+f"(c[1]), "+f"(c[2]), "+f"(c[3])
        : "r"(a[0]), "r"(a[1]), "r"(a[2]), "r"(a[3]), "r"(b0), "r"(b1));
}
__device__ __forceinline__ void mma_f_init(float c[4], const uint32_t a[4],
                                           uint32_t b0, uint32_t b1) {
    const float z = 0.f;
    asm volatile(
        "mma.sync.aligned.m16n8k16.row.col.f32.f16.f16.f32 "
        "{%0,%1,%2,%3},{%4,%5,%6,%7},{%8,%9},{%10,%10,%10,%10};"
        : "=f"(c[0]), "=f"(c[1]), "=f"(c[2]), "=f"(c[3])
        : "r"(a[0]), "r"(a[1]), "r"(a[2]), "r"(a[3]), "r"(b0), "r"(b1), "f"(z));
}

__device__ __forceinline__ uint32_t pack_h2(float v0, float v1) {
    uint32_t r;
    asm("cvt.rn.f16x2.f32 %0, %1, %2;" : "=r"(r) : "f"(v1), "f"(v0));
    return r;
}
__device__ __forceinline__ uint32_t h2_bias_relu(uint32_t h, uint32_t b) {
    uint32_t r;
    const uint32_t one = 0x3C003C00u;
    asm("fma.rn.relu.f16x2 %0, %1, %2, %3;" : "=r"(r) : "r"(h), "r"(one), "r"(b));
    return r;
}

// one hidden layer for ONE stream (32 rows): C = A x W^T
template <int KT>
__device__ __forceinline__ void run_layer(uint32_t C[2][8][2],
                                          const uint32_t A[2][4][4],
                                          const uint4* __restrict__ fh,
                                          int lane) {
#pragma unroll
    for (int kt = 0; kt < KT; kt++) {
#pragma unroll
        for (int i = 0; i < 4; i++) {
            uint4 bh = fh[(i * 4 + kt) * 32 + lane];
            if (kt == 0) {
                mma_h_init(C[0][2 * i],     A[0][0], bh.x, bh.y);
                mma_h_init(C[0][2 * i + 1], A[0][0], bh.z, bh.w);
                mma_h_init(C[1][2 * i],     A[1][0], bh.x, bh.y);
                mma_h_init(C[1][2 * i + 1], A[1][0], bh.z, bh.w);
            } else {
                mma_h_acc(C[0][2 * i],     A[0][kt], bh.x, bh.y);
                mma_h_acc(C[0][2 * i + 1], A[0][kt], bh.z, bh.w);
                mma_h_acc(C[1][2 * i],     A[1][kt], bh.x, bh.y);
                mma_h_acc(C[1][2 * i + 1], A[1][kt], bh.z, bh.w);
            }
        }
    }
}

// bias+relu epilogue for ONE stream: C -> A (in place of next layer's input)
__device__ __forceinline__ void epi_layer(uint32_t A[2][4][4],
                                          const uint32_t C[2][8][2],
                                          const uint32_t* __restrict__ bih) {
#pragma unroll
    for (int i = 0; i < 4; i++) {
        uint32_t b20 = bih[(2 * i) * 4];
        uint32_t b21 = bih[(2 * i + 1) * 4];
#pragma unroll
        for (int mt = 0; mt < 2; mt++) {
            A[mt][i][0] = h2_bias_relu(C[mt][2 * i][0],     b20);
            A[mt][i][1] = h2_bias_relu(C[mt][2 * i][1],     b20);
            A[mt][i][2] = h2_bias_relu(C[mt][2 * i + 1][0], b21);
            A[mt][i][3] = h2_bias_relu(C[mt][2 * i + 1][1], b21);
        }
    }
}

// issue cp.async for one 32-row slice (no commit)
__device__ __forceinline__ void prefetch32(const float* __restrict__ x,
                                           long rb, int n, uint32_t dst,
                                           int rowoff, int seg) {
#pragma unroll
    for (int c = 0; c < 8; c++) {
        int row = 4 * c + rowoff;
        long gr = rb + row;
        int ok = gr < n;
        const float* g = x + (ok ? gr : (long)(n - 1)) * 32 + seg * 4;
        uint32_t d = dst + (uint32_t)(row * (XB_STRIDE * 4) + seg * 16);
        int sz = ok ? 16 : 0;
        asm volatile("cp.async.cg.shared.global [%0], [%1], 16, %2;"
                     :: "r"(d), "l"(g), "r"(sz) : "memory");
    }
}

__device__ __forceinline__ void build_A(uint32_t A[2][4][4],
                                        const float* __restrict__ xb,
                                        int td4, int q) {
#pragma unroll
    for (int mt = 0; mt < 2; mt++) {
        int rr = mt * 16 + td4;
        const float* p0 = xb + rr * XB_STRIDE + 2 * q;
        const float* p1 = p0 + 8 * XB_STRIDE;
#pragma unroll
        for (int kt = 0; kt < 2; kt++) {
            float2 a = *(const float2*)(p0 + kt * 16);
            float2 b = *(const float2*)(p1 + kt * 16);
            float2 c = *(const float2*)(p0 + kt * 16 + 8);
            float2 d = *(const float2*)(p1 + kt * 16 + 8);
            A[mt][kt][0] = pack_h2(a.x, a.y);
            A[mt][kt][1] = pack_h2(b.x, b.y);
            A[mt][kt][2] = pack_h2(c.x, c.y);
            A[mt][kt][3] = pack_h2(d.x, d.y);
        }
    }
}

__global__ void __launch_bounds__(256, 1)
mlp_hmma8_kernel(const float* __restrict__ x,
                 const float* __restrict__ W0, const float* __restrict__ b0,
                 const float* __restrict__ W1, const float* __restrict__ b1,
                 const float* __restrict__ W2, const float* __restrict__ b2,
                 const float* __restrict__ W3, const float* __restrict__ b3,
                 const float* __restrict__ W4, const float* __restrict__ b4,
                 float* __restrict__ out, int n, int ntiles)
{
    extern __shared__ char sm[];
    uint4*    FH  = (uint4*)(sm + FH_OFF);
    float*    XB  = (float*)(sm + XB_OFF);
    uint4*    FH4 = (uint4*)(sm + FH4_OFF);
    uint32_t* BIH = (uint32_t*)(sm + BIH_OFF);
    float*    B4p = (float*)(sm + B4P_OFF);

    const int tid  = threadIdx.x;
    const int warp = tid >> 5;
    const int lane = tid & 31;
    const int q    = lane & 3;
    const int td4  = lane >> 2;

    // per-warp buffers: [s0b0, s0b1, s1b0, s1b1]
    float* XW = XB + warp * 4 * XW_FLOATS;
    uint32_t xw_u32;
    asm("{ .reg .u64 t; cvta.to.shared.u64 t, %1; cvt.u32.u64 %0, t; }"
        : "=r"(xw_u32) : "l"((const void*)XW));

    const int pf_rowoff = lane >> 3;
    const int pf_seg    = lane & 7;

    // ---- prefetch tile0 (both streams) -> buf0 ----
    {
        long rb = (long)blockIdx.x * 512 + warp * 64;
        prefetch32(x, rb,      n, xw_u32,                  pf_rowoff, pf_seg);
        prefetch32(x, rb + 32, n, xw_u32 + 2 * XW_BYTES,   pf_rowoff, pf_seg);
        asm volatile("cp.async.commit_group;" ::: "memory");
    }

    // ---- stage weights ----
    {
        const float* Ws[4] = {W0, W1, W2, W3};
        for (int idx = tid; idx < 4 * 4 * 4 * 32; idx += 256) {
            int ln = idx & 31;
            int kt = (idx >> 5) & 3;
            int i  = (idx >> 7) & 3;
            int l  = idx >> 9;
            int lq = ln & 3, ltd4 = ln >> 2;
            const int K = (l == 0) ? 32 : 64;
            const float* W = Ws[l];
            uint32_t rh[4];
#pragma unroll
            for (int r = 0; r < 4; r++) {
                int nn = 8 * (2 * i + (r >> 1)) + ltd4;
                int k  = 16 * kt + 2 * lq + (r & 1) * 8;
                float w0 = (k     < K) ? W[nn * K + k]     : 0.f;
                float w1 = (k + 1 < K) ? W[nn * K + k + 1] : 0.f;
                rh[r] = pack_h2(w0, w1);
            }
            FH[idx] = make_uint4(rh[0], rh[1], rh[2], rh[3]);
        }
        if (tid < 64) {
            int ktp = tid >> 5, ln = tid & 31;
            int lq = ln & 3, ltd4 = ln >> 2;
            uint32_t rh[4];
#pragma unroll
            for (int r = 0; r < 4; r++) {
                int kt = 2 * ktp + (r >> 1);
                int k  = 16 * kt + 2 * lq + (r & 1) * 8;
                float w0 = (ltd4 < 3) ? W4[ltd4 * 64 + k]     : 0.f;
                float w1 = (ltd4 < 3) ? W4[ltd4 * 64 + k + 1] : 0.f;
                rh[r] = pack_h2(w0, w1);
            }
            FH4[tid] = make_uint4(rh[0], rh[1], rh[2], rh[3]);
        }
        if (tid < 128) {
            int l = tid >> 5, idx = tid & 31;
            int nt = idx >> 2, bq = idx & 3;
            const float* bl = (l == 0) ? b0 : (l == 1) ? b1 : (l == 2) ? b2 : b3;
            BIH[tid] = pack_h2(bl[8 * nt + 2 * bq], bl[8 * nt + 2 * bq + 1]);
        }
        if (tid < 8) B4p[tid] = (tid < 3) ? b4[tid] : 0.f;
    }
    __syncthreads();

    const uint4 f0 = FH4[lane];
    const uint4 f1 = FH4[32 + lane];
    const float bc0 = B4p[2 * q];
    const float bc1 = B4p[2 * q + 1];
    const uint32_t* bih = BIH + q;

    uint32_t A0[2][4][4], A1[2][4][4];
    uint32_t C0[2][8][2], C1[2][8][2];

    // ---- prologue: A for tile0, start tile1 prefetch ----
    asm volatile("cp.async.wait_group 0;" ::: "memory");
    __syncwarp();
    build_A(A0, XW, td4, q);
    build_A(A1, XW + 2 * XW_FLOATS, td4, q);
    {
        long t1 = (long)blockIdx.x + gridDim.x;
        if (t1 < ntiles) {
            long rb = t1 * 512 + warp * 64;
            prefetch32(x, rb,      n, xw_u32 + XW_BYTES,      pf_rowoff, pf_seg);
            prefetch32(x, rb + 32, n, xw_u32 + 3 * XW_BYTES,  pf_rowoff, pf_seg);
        }
        asm volatile("cp.async.commit_group;" ::: "memory");
    }

    int it = 0;
    for (int tile = blockIdx.x; tile < ntiles; tile += gridDim.x, it++) {
        const int cur = it & 1;

        // ---- interleaved two-stream layer pipeline ----
        run_layer<2>(C0, A0, FH, lane);
        run_layer<2>(C1, A1, FH, lane);

        epi_layer(A0, C0, bih);             // C0 drained (64 MMAs ago)
        run_layer<4>(C0, A0, FH + 512, lane);
        epi_layer(A1, C1, bih);
        run_layer<4>(C1, A1, FH + 512, lane);

        epi_layer(A0, C0, bih + 32);
        run_layer<4>(C0, A0, FH + 1024, lane);
        epi_layer(A1, C1, bih + 32);
        run_layer<4>(C1, A1, FH + 1024, lane);

        epi_layer(A0, C0, bih + 64);
        run_layer<4>(C0, A0, FH + 1536, lane);
        epi_layer(A1, C1, bih + 64);
        run_layer<4>(C1, A1, FH + 1536, lane);

        float D0a[4], D0b[4], D1a[4], D1b[4];
        epi_layer(A0, C0, bih + 96);
        mma_f_init(D0a, A0[0][0], f0.x, f0.y);
        mma_f_init(D0b, A0[1][0], f0.x, f0.y);
        mma_f_acc(D0a, A0[0][1], f0.z, f0.w);
        mma_f_acc(D0b, A0[1][1], f0.z, f0.w);
        mma_f_acc(D0a, A0[0][2], f1.x, f1.y);
        mma_f_acc(D0b, A0[1][2], f1.x, f1.y);
        mma_f_acc(D0a, A0[0][3], f1.z, f1.w);
        mma_f_acc(D0b, A0[1][3], f1.z, f1.w);
        epi_layer(A1, C1, bih + 96);
        mma_f_init(D1a, A1[0][0], f0.x, f0.y);
        mma_f_init(D1b, A1[1][0], f0.x, f0.y);
        mma_f_acc(D1a, A1[0][1], f0.z, f0.w);
        mma_f_acc(D1b, A1[1][1], f0.z, f0.w);
        mma_f_acc(D1a, A1[0][2], f1.x, f1.y);
        mma_f_acc(D1b, A1[1][2], f1.x, f1.y);
        mma_f_acc(D1a, A1[0][3], f1.z, f1.w);
        mma_f_acc(D1b, A1[1][3], f1.z, f1.w);

        // ---- overlapped tail: wait next X, rebuild A, prefetch tile+2s ----
        asm volatile("cp.async.wait_group 0;" ::: "memory");
        __syncwarp();
        if (tile + gridDim.x < ntiles) {
            build_A(A0, XW + (cur ^ 1) * XW_FLOATS, td4, q);
            build_A(A1, XW + (2 + (cur ^ 1)) * XW_FLOATS, td4, q);
        }
        {
            long t2 = (long)tile + 2L * gridDim.x;
            if (t2 < ntiles) {
                long rb = t2 * 512 + warp * 64;
                prefetch32(x, rb,      n, xw_u32 + (uint32_t)cur * XW_BYTES,
                           pf_rowoff, pf_seg);
                prefetch32(x, rb + 32, n, xw_u32 + (uint32_t)(2 + cur) * XW_BYTES,
                           pf_rowoff, pf_seg);
            }
            asm volatile("cp.async.commit_group;" ::: "memory");
        }

        // ---- sigmoid + store (overlaps A-build latency) ----
        {
            const long rbase = (long)tile * 512 + warp * 64;
#pragma unroll
            for (int s = 0; s < 2; s++) {
                const long sb = rbase + s * 32;
#pragma unroll
                for (int mt = 0; mt < 2; mt++) {
                    const float* Dp = (s == 0) ? ((mt == 0) ? D0a : D0b)
                                               : ((mt == 0) ? D1a : D1b);
                    long r0 = sb + mt * 16 + td4;
                    long r1 = r0 + 8;
                    float o0 = __fdividef(1.f, 1.f + __expf(-(Dp[0] + bc0)));
                    float o1 = __fdividef(1.f, 1.f + __expf(-(Dp[1] + bc1)));
                    float o2 = __fdividef(1.f, 1.f + __expf(-(Dp[2] + bc0)));
                    float o3 = __fdividef(1.f, 1.f + __expf(-(Dp[3] + bc1)));
                    if (q == 0) {
                        if (r0 < n) { out[r0 * 3 + 0] = o0; out[r0 * 3 + 1] = o1; }
                        if (r1 < n) { out[r1 * 3 + 0] = o2; out[r1 * 3 + 1] = o3; }
                    } else if (q == 1) {
                        if (r0 < n) out[r0 * 3 + 2] = o0;
                        if (r1 < n) out[r1 * 3 + 2] = o2;
                    }
                }
            }
        }
    }
}

extern "C" void kernel_launch(void* const* d_in, const int* in_sizes, int n_in,
                              void* d_out, int out_size) {
    const float* x  = (const float*)d_in[0];
    const float* W0 = (const float*)d_in[1];
    const float* b0 = (const float*)d_in[2];
    const float* W1 = (const float*)d_in[3];
    const float* b1 = (const float*)d_in[4];
    const float* W2 = (const float*)d_in[5];
    const float* b2 = (const float*)d_in[6];
    const float* W3 = (const float*)d_in[7];
    const float* b3 = (const float*)d_in[8];
    const float* W4 = (const float*)d_in[9];
    const float* b4 = (const float*)d_in[10];
    float* out = (float*)d_out;

    const int n = in_sizes[0] / 32;
    const int ntiles = (n + 511) / 512;

    cudaFuncSetAttribute(mlp_hmma8_kernel,
                         cudaFuncAttributeMaxDynamicSharedMemorySize, SMEM_BYTES);

    int blocks = 148;
    if (ntiles < blocks) blocks = ntiles;

    mlp_hmma8_kernel<<<blocks, 256, SMEM_BYTES>>>(
        x, W0, b0, W1, b1, W2, b2, W3, b3, W4, b4, out, n, ntiles);
}

// round 15
// speedup vs baseline: 1.0472x; 1.0472x over previous
#include <cuda_runtime.h>
#include <cuda_fp16.h>
#include <stdint.h>
#include <math.h>

// ---------------------------------------------------------------------------
// Fused 5-layer MLP (32->64->64->64->64->3, ReLU hidden, sigmoid out).
// mma.sync m16n8k16 fp16-in/fp16-accum hidden layers (D-frag == next A-frag),
// fused fma.rn.relu.f16x2 epilogues, fp32-accum final MMA + sigmoid.
// R15: explicit weight-fragment software pipeline — a rolling uint4 'bh' is
// always one (kt,i) slot ahead, prefetched across layer boundaries AND across
// tiles, so no MMA group ever waits on its LDS.128. 2 CTAs/SM, 4 warps/SMSP,
// warp-private double-buffered cp.async X slices, no CTA barrier in the loop.
// ---------------------------------------------------------------------------

#define FH_OFF     0           // 4l*4i*4kt*32lane*16B = 32768
#define XB_OFF     32768       // 8 warps * 2 bufs * 32 rows * 36 floats * 4B
#define XB_STRIDE  36
#define XW_FLOATS  (32 * XB_STRIDE)      // 1152 floats per warp-buffer
#define XW_BYTES   (XW_FLOATS * 4)       // 4608
#define FH4_OFF    106496
#define BIH_OFF    107520
#define B4P_OFF    108032
#define SMEM_BYTES 108064

__device__ __forceinline__ void mma_h_acc(uint32_t c[2], const uint32_t a[4],
                                          uint32_t b0, uint32_t b1) {
    asm volatile(
        "mma.sync.aligned.m16n8k16.row.col.f16.f16.f16.f16 "
        "{%0,%1},{%2,%3,%4,%5},{%6,%7},{%0,%1};"
        : "+r"(c[0]), "+r"(c[1])
        : "r"(a[0]), "r"(a[1]), "r"(a[2]), "r"(a[3]), "r"(b0), "r"(b1));
}
__device__ __forceinline__ void mma_h_init(uint32_t c[2], const uint32_t a[4],
                                           uint32_t b0, uint32_t b1) {
    const uint32_t z = 0;
    asm volatile(
        "mma.sync.aligned.m16n8k16.row.col.f16.f16.f16.f16 "
        "{%0,%1},{%2,%3,%4,%5},{%6,%7},{%8,%8};"
        : "=r"(c[0]), "=r"(c[1])
        : "r"(a[0]), "r"(a[1]), "r"(a[2]), "r"(a[3]), "r"(b0), "r"(b1), "r"(z));
}
__device__ __forceinline__ void mma_f_acc(float c[4], const uint32_t a[4],
                                          uint32_t b0, uint32_t b1) {
    asm volatile(
        "mma.sync.aligned.m16n8k16.row.col.f32.f16.f16.f32 "
        "{%0,%1,%2,%3},{%4,%5,%6,%7},{%8,%9},{%0,%1,%2,%3};"
        : "+f"(c[0]), "+f"(c[1]), "+f"(c[2]), "+f"(c[3])
        : "r"(a[0]), "r"(a[1]), "r"(a[2]), "r"(a[3]), "r"(b0), "r"(b1));
}
__device__ __forceinline__ void mma_f_init(float c[4], const uint32_t a[4],
                                           uint32_t b0, uint32_t b1) {
    const float z = 0.f;
    asm volatile(
        "mma.sync.aligned.m16n8k16.row.col.f32.f16.f16.f32 "
        "{%0,%1,%2,%3},{%4,%5,%6,%7},{%8,%9},{%10,%10,%10,%10};"
        : "=f"(c[0]), "=f"(c[1]), "=f"(c[2]), "=f"(c[3])
        : "r"(a[0]), "r"(a[1]), "r"(a[2]), "r"(a[3]), "r"(b0), "r"(b1), "f"(z));
}

__device__ __forceinline__ uint32_t pack_h2(float v0, float v1) {
    uint32_t r;
    asm("cvt.rn.f16x2.f32 %0, %1, %2;" : "=r"(r) : "f"(v1), "f"(v0));
    return r;
}
__device__ __forceinline__ uint32_t h2_bias_relu(uint32_t h, uint32_t b) {
    uint32_t r;
    const uint32_t one = 0x3C003C00u;
    asm("fma.rn.relu.f16x2 %0, %1, %2, %3;" : "=r"(r) : "r"(h), "r"(one), "r"(b));
    return r;
}

// one hidden layer with rolling weight-fragment pipeline.
// 'bh' enters holding fh[(i=0,kt=0)]; returns fhn[lane] (next layer's first).
template <int KT>
__device__ __forceinline__ uint4 run_layer_pl(uint32_t C[2][8][2],
                                              const uint32_t A[2][4][4],
                                              const uint4* __restrict__ fh,
                                              const uint4* __restrict__ fhn,
                                              int lane, uint4 bh) {
#pragma unroll
    for (int kt = 0; kt < KT; kt++) {
#pragma unroll
        for (int i = 0; i < 4; i++) {
            uint4 nx;
            if (i == 3 && kt == KT - 1) {
                nx = fhn[lane];                       // next layer, (0,0)
            } else {
                int ni  = (i == 3) ? 0 : i + 1;
                int nkt = (i == 3) ? kt + 1 : kt;
                nx = fh[(ni * 4 + nkt) * 32 + lane];
            }
            if (kt == 0) {
                mma_h_init(C[0][2 * i],     A[0][0], bh.x, bh.y);
                mma_h_init(C[0][2 * i + 1], A[0][0], bh.z, bh.w);
                mma_h_init(C[1][2 * i],     A[1][0], bh.x, bh.y);
                mma_h_init(C[1][2 * i + 1], A[1][0], bh.z, bh.w);
            } else {
                mma_h_acc(C[0][2 * i],     A[0][kt], bh.x, bh.y);
                mma_h_acc(C[0][2 * i + 1], A[0][kt], bh.z, bh.w);
                mma_h_acc(C[1][2 * i],     A[1][kt], bh.x, bh.y);
                mma_h_acc(C[1][2 * i + 1], A[1][kt], bh.z, bh.w);
            }
            bh = nx;
        }
    }
    return bh;
}

__device__ __forceinline__ void prefetch_slice(const float* __restrict__ x,
                                               long rb, int n, uint32_t dst,
                                               int rowoff, int seg) {
#pragma unroll
    for (int c = 0; c < 8; c++) {
        int row = 4 * c + rowoff;
        long gr = rb + row;
        int ok = gr < n;
        const float* g = x + (ok ? gr : (long)(n - 1)) * 32 + seg * 4;
        uint32_t d = dst + (uint32_t)(row * (XB_STRIDE * 4) + seg * 16);
        int sz = ok ? 16 : 0;
        asm volatile("cp.async.cg.shared.global [%0], [%1], 16, %2;"
                     :: "r"(d), "l"(g), "r"(sz) : "memory");
    }
    asm volatile("cp.async.commit_group;" ::: "memory");
}

__device__ __forceinline__ void build_A(uint32_t A[2][4][4],
                                        const float* __restrict__ xb,
                                        int td4, int q) {
#pragma unroll
    for (int mt = 0; mt < 2; mt++) {
        int rr = mt * 16 + td4;
        const float* p0 = xb + rr * XB_STRIDE + 2 * q;
        const float* p1 = p0 + 8 * XB_STRIDE;
#pragma unroll
        for (int kt = 0; kt < 2; kt++) {
            float2 a = *(const float2*)(p0 + kt * 16);
            float2 b = *(const float2*)(p1 + kt * 16);
            float2 c = *(const float2*)(p0 + kt * 16 + 8);
            float2 d = *(const float2*)(p1 + kt * 16 + 8);
            A[mt][kt][0] = pack_h2(a.x, a.y);
            A[mt][kt][1] = pack_h2(b.x, b.y);
            A[mt][kt][2] = pack_h2(c.x, c.y);
            A[mt][kt][3] = pack_h2(d.x, d.y);
        }
    }
}

__global__ void __launch_bounds__(256, 2)
mlp_hmma9_kernel(const float* __restrict__ x,
                 const float* __restrict__ W0, const float* __restrict__ b0,
                 const float* __restrict__ W1, const float* __restrict__ b1,
                 const float* __restrict__ W2, const float* __restrict__ b2,
                 const float* __restrict__ W3, const float* __restrict__ b3,
                 const float* __restrict__ W4, const float* __restrict__ b4,
                 float* __restrict__ out, int n, int ntiles)
{
    extern __shared__ char sm[];
    uint4*    FH  = (uint4*)(sm + FH_OFF);
    float*    XB  = (float*)(sm + XB_OFF);
    uint4*    FH4 = (uint4*)(sm + FH4_OFF);
    uint32_t* BIH = (uint32_t*)(sm + BIH_OFF);
    float*    B4p = (float*)(sm + B4P_OFF);

    const int tid  = threadIdx.x;
    const int warp = tid >> 5;
    const int lane = tid & 31;
    const int q    = lane & 3;
    const int td4  = lane >> 2;

    float* XW = XB + warp * 2 * XW_FLOATS;
    uint32_t xw_u32;
    asm("{ .reg .u64 t; cvta.to.shared.u64 t, %1; cvt.u32.u64 %0, t; }"
        : "=r"(xw_u32) : "l"((const void*)XW));

    const int pf_rowoff = lane >> 3;
    const int pf_seg    = lane & 7;

    // ---- prefetch tile0 slice -> buf0 ----
    prefetch_slice(x, (long)blockIdx.x * 256 + warp * 32, n, xw_u32,
                   pf_rowoff, pf_seg);

    // ---- stage weights (whole CTA), one barrier ----
    {
        const float* Ws[4] = {W0, W1, W2, W3};
        for (int idx = tid; idx < 4 * 4 * 4 * 32; idx += 256) {
            int ln = idx & 31;
            int kt = (idx >> 5) & 3;
            int i  = (idx >> 7) & 3;
            int l  = idx >> 9;
            int lq = ln & 3, ltd4 = ln >> 2;
            const int K = (l == 0) ? 32 : 64;
            const float* W = Ws[l];
            uint32_t rh[4];
#pragma unroll
            for (int r = 0; r < 4; r++) {
                int nn = 8 * (2 * i + (r >> 1)) + ltd4;
                int k  = 16 * kt + 2 * lq + (r & 1) * 8;
                float w0 = (k     < K) ? W[nn * K + k]     : 0.f;
                float w1 = (k + 1 < K) ? W[nn * K + k + 1] : 0.f;
                rh[r] = pack_h2(w0, w1);
            }
            FH[idx] = make_uint4(rh[0], rh[1], rh[2], rh[3]);
        }
        if (tid < 64) {
            int ktp = tid >> 5, ln = tid & 31;
            int lq = ln & 3, ltd4 = ln >> 2;
            uint32_t rh[4];
#pragma unroll
            for (int r = 0; r < 4; r++) {
                int kt = 2 * ktp + (r >> 1);
                int k  = 16 * kt + 2 * lq + (r & 1) * 8;
                float w0 = (ltd4 < 3) ? W4[ltd4 * 64 + k]     : 0.f;
                float w1 = (ltd4 < 3) ? W4[ltd4 * 64 + k + 1] : 0.f;
                rh[r] = pack_h2(w0, w1);
            }
            FH4[tid] = make_uint4(rh[0], rh[1], rh[2], rh[3]);
        }
        if (tid < 128) {
            int l = tid >> 5, idx = tid & 31;
            int nt = idx >> 2, bq = idx & 3;
            const float* bl = (l == 0) ? b0 : (l == 1) ? b1 : (l == 2) ? b2 : b3;
            BIH[tid] = pack_h2(bl[8 * nt + 2 * bq], bl[8 * nt + 2 * bq + 1]);
        }
        if (tid < 8) B4p[tid] = (tid < 3) ? b4[tid] : 0.f;
    }
    __syncthreads();

    const uint4 f0 = FH4[lane];
    const uint4 f1 = FH4[32 + lane];
    const float bc0 = B4p[2 * q];
    const float bc1 = B4p[2 * q + 1];

    uint32_t A[2][4][4];
    uint32_t C[2][8][2];

    // ---- prologue: A for tile0, start tile1 prefetch, preload first frag ----
    asm volatile("cp.async.wait_group 0;" ::: "memory");
    __syncwarp();
    build_A(A, XW, td4, q);
    {
        long t1 = (long)blockIdx.x + gridDim.x;
        if (t1 < ntiles)
            prefetch_slice(x, t1 * 256 + warp * 32, n, xw_u32 + XW_BYTES,
                           pf_rowoff, pf_seg);
    }
    uint4 bh = FH[lane];   // layer0, (kt=0, i=0)

    int it = 0;
    for (int tile = blockIdx.x; tile < ntiles; tile += gridDim.x, it++) {
        const int cur = it & 1;

        // ---- 4 hidden layers, rolling weight pipeline across boundaries ----
        bh = run_layer_pl<2>(C, A, FH,        FH + 512,  lane, bh);
        {
            const uint32_t* bih = BIH + q;
#pragma unroll
            for (int i = 0; i < 4; i++) {
                uint32_t b20 = bih[(2 * i) * 4];
                uint32_t b21 = bih[(2 * i + 1) * 4];
#pragma unroll
                for (int mt = 0; mt < 2; mt++) {
                    A[mt][i][0] = h2_bias_relu(C[mt][2 * i][0],     b20);
                    A[mt][i][1] = h2_bias_relu(C[mt][2 * i][1],     b20);
                    A[mt][i][2] = h2_bias_relu(C[mt][2 * i + 1][0], b21);
                    A[mt][i][3] = h2_bias_relu(C[mt][2 * i + 1][1], b21);
                }
            }
        }
        bh = run_layer_pl<4>(C, A, FH + 512,  FH + 1024, lane, bh);
        {
            const uint32_t* bih = BIH + 32 + q;
#pragma unroll
            for (int i = 0; i < 4; i++) {
                uint32_t b20 = bih[(2 * i) * 4];
                uint32_t b21 = bih[(2 * i + 1) * 4];
#pragma unroll
                for (int mt = 0; mt < 2; mt++) {
                    A[mt][i][0] = h2_bias_relu(C[mt][2 * i][0],     b20);
                    A[mt][i][1] = h2_bias_relu(C[mt][2 * i][1],     b20);
                    A[mt][i][2] = h2_bias_relu(C[mt][2 * i + 1][0], b21);
                    A[mt][i][3] = h2_bias_relu(C[mt][2 * i + 1][1], b21);
                }
            }
        }
        bh = run_layer_pl<4>(C, A, FH + 1024, FH + 1536, lane, bh);
        {
            const uint32_t* bih = BIH + 64 + q;
#pragma unroll
            for (int i = 0; i < 4; i++) {
                uint32_t b20 = bih[(2 * i) * 4];
                uint32_t b21 = bih[(2 * i + 1) * 4];
#pragma unroll
                for (int mt = 0; mt < 2; mt++) {
                    A[mt][i][0] = h2_bias_relu(C[mt][2 * i][0],     b20);
                    A[mt][i][1] = h2_bias_relu(C[mt][2 * i][1],     b20);
                    A[mt][i][2] = h2_bias_relu(C[mt][2 * i + 1][0], b21);
                    A[mt][i][3] = h2_bias_relu(C[mt][2 * i + 1][1], b21);
                }
            }
        }
        // last hidden layer: roll into next tile's layer0 first fragment
        bh = run_layer_pl<4>(C, A, FH + 1536, FH,        lane, bh);
        {
            const uint32_t* bih = BIH + 96 + q;
#pragma unroll
            for (int i = 0; i < 4; i++) {
                uint32_t b20 = bih[(2 * i) * 4];
                uint32_t b21 = bih[(2 * i + 1) * 4];
#pragma unroll
                for (int mt = 0; mt < 2; mt++) {
                    A[mt][i][0] = h2_bias_relu(C[mt][2 * i][0],     b20);
                    A[mt][i][1] = h2_bias_relu(C[mt][2 * i][1],     b20);
                    A[mt][i][2] = h2_bias_relu(C[mt][2 * i + 1][0], b21);
                    A[mt][i][3] = h2_bias_relu(C[mt][2 * i + 1][1], b21);
                }
            }
        }

        // ---- final 64->3 fp32-accum MMA ----
        float D0[4], D1[4];
        mma_f_init(D0, A[0][0], f0.x, f0.y);
        mma_f_init(D1, A[1][0], f0.x, f0.y);
        mma_f_acc(D0, A[0][1], f0.z, f0.w);
        mma_f_acc(D1, A[1][1], f0.z, f0.w);
        mma_f_acc(D0, A[0][2], f1.x, f1.y);
        mma_f_acc(D1, A[1][2], f1.x, f1.y);
        mma_f_acc(D0, A[0][3], f1.z, f1.w);
        mma_f_acc(D1, A[1][3], f1.z, f1.w);

        // ---- overlapped tail: wait X, prefetch tile+2s FIRST, rebuild A ----
        asm volatile("cp.async.wait_group 0;" ::: "memory");
        __syncwarp();
        {
            long t2 = (long)tile + 2L * gridDim.x;
            if (t2 < ntiles)
                prefetch_slice(x, t2 * 256 + warp * 32, n,
                               xw_u32 + (uint32_t)cur * XW_BYTES,
                               pf_rowoff, pf_seg);
        }
        if (tile + gridDim.x < ntiles)
            build_A(A, XW + (cur ^ 1) * XW_FLOATS, td4, q);

        // ---- sigmoid + store (overlaps A-build latency) ----
        {
            const long rbase = (long)tile * 256 + warp * 32;
#pragma unroll
            for (int mt = 0; mt < 2; mt++) {
                const float* Dp = (mt == 0) ? D0 : D1;
                long r0 = rbase + mt * 16 + td4;
                long r1 = r0 + 8;
                float o0 = __fdividef(1.f, 1.f + __expf(-(Dp[0] + bc0)));
                float o1 = __fdividef(1.f, 1.f + __expf(-(Dp[1] + bc1)));
                float o2 = __fdividef(1.f, 1.f + __expf(-(Dp[2] + bc0)));
                float o3 = __fdividef(1.f, 1.f + __expf(-(Dp[3] + bc1)));
                if (q == 0) {
                    if (r0 < n) { out[r0 * 3 + 0] = o0; out[r0 * 3 + 1] = o1; }
                    if (r1 < n) { out[r1 * 3 + 0] = o2; out[r1 * 3 + 1] = o3; }
                } else if (q == 1) {
                    if (r0 < n) out[r0 * 3 + 2] = o0;
                    if (r1 < n) out[r1 * 3 + 2] = o2;
                }
            }
        }
    }
}

extern "C" void kernel_launch(void* const* d_in, const int* in_sizes, int n_in,
                              void* d_out, int out_size) {
    const float* x  = (const float*)d_in[0];
    const float* W0 = (const float*)d_in[1];
    const float* b0 = (const float*)d_in[2];
    const float* W1 = (const float*)d_in[3];
    const float* b1 = (const float*)d_in[4];
    const float* W2 = (const float*)d_in[5];
    const float* b2 = (const float*)d_in[6];
    const float* W3 = (const float*)d_in[7];
    const float* b3 = (const float*)d_in[8];
    const float* W4 = (const float*)d_in[9];
    const float* b4 = (const float*)d_in[10];
    float* out = (float*)d_out;

    const int n = in_sizes[0] / 32;
    const int ntiles = (n + 255) / 256;

    cudaFuncSetAttribute(mlp_hmma9_kernel,
                         cudaFuncAttributeMaxDynamicSharedMemorySize, SMEM_BYTES);

    int blocks = 148 * 2;
    if (ntiles < blocks) blocks = ntiles;

    mlp_hmma9_kernel<<<blocks, 256, SMEM_BYTES>>>(
        x, W0, b0, W1, b1, W2, b2, W3, b3, W4, b4, out, n, ntiles);
}